// round 5
// baseline (speedup 1.0000x reference)
#include <cuda_runtime.h>
#include <math.h>

// Problem constants
#define LSEQ 8192
#define NFFT 16384          // 2*LSEQ = 4^7
#define DM   768
#define EMB  33
#define FO   64
#define SHIFT_C 0.05f
#define NT   256            // FFT threads per CTA (one radix-64 column per thread)

// Pad 2 float2 per 128 float2.  Verified: P1 (stride-256) conflict-free,
// P2 (g*256+j+4r) 2-way, P3 float4 aligned + 4-phase.  PHYS(i)=i+2*(i>>7).
#define DPAD 16640                                       // PHYS(16383)=16637
#define SMEM_BYTES (DPAD * (int)sizeof(float2))          // 133120 B

// ---------------- scratch (device globals: no allocations allowed) ----------
__device__ float  g_S[LSEQ * FO];                        // post-MLP activations
__device__ float  g_k[DM * LSEQ];                        // filter k[d][l]
__device__ __align__(16) float2 g_Kf[(size_t)DM * NFFT]; // (spectrum + D)/N, scrambled

// e^{-2*pi*i*c/64}, c = 0..15 (forward rotations)
__constant__ float2 cROT[16] = {
    { 1.0f, 0.0f },
    { 0.99518472667219693f, -0.098017140329560602f },
    { 0.98078528040323044f, -0.19509032201612827f },
    { 0.95694033573220886f, -0.29028467725446233f },
    { 0.92387953251128674f, -0.38268343236508977f },
    { 0.88192126434835503f, -0.47139673682599764f },
    { 0.83146961230254524f, -0.55557023301960222f },
    { 0.77301045336273699f, -0.63439328416364549f },
    { 0.70710678118654752f, -0.70710678118654752f },
    { 0.63439328416364549f, -0.77301045336273699f },
    { 0.55557023301960222f, -0.83146961230254524f },
    { 0.47139673682599764f, -0.88192126434835503f },
    { 0.38268343236508977f, -0.92387953251128674f },
    { 0.29028467725446233f, -0.95694033573220886f },
    { 0.19509032201612827f, -0.98078528040323044f },
    { 0.098017140329560602f, -0.99518472667219693f }
};

// ---------------- complex helpers ----------------
__device__ __forceinline__ float2 cadd(float2 a, float2 b){ return make_float2(a.x+b.x, a.y+b.y); }
__device__ __forceinline__ float2 csub(float2 a, float2 b){ return make_float2(a.x-b.x, a.y-b.y); }
__device__ __forceinline__ float2 cmul(float2 a, float2 b){
    return make_float2(a.x*b.x - a.y*b.y, a.x*b.y + a.y*b.x);
}
__device__ __forceinline__ float2 conjf2(float2 a){ return make_float2(a.x, -a.y); }

// radix-4 DIF forward core (no twiddle)
__device__ __forceinline__ void bf4f(float2 x0, float2 x1, float2 x2, float2 x3,
                                     float2& a0, float2& a1, float2& a2, float2& a3) {
    float2 t0 = cadd(x0, x2), t1 = csub(x0, x2);
    float2 t2 = cadd(x1, x3), t3 = csub(x1, x3);
    float2 mi = make_float2(t3.y, -t3.x);                // -i * t3
    a0 = cadd(t0, t2);
    a1 = cadd(t1, mi);
    a2 = csub(t0, t2);
    a3 = csub(t1, mi);
}
// radix-4 inverse core (unscaled)
__device__ __forceinline__ void bf4i(float2 x0, float2 x1, float2 x2, float2 x3,
                                     float2& a0, float2& a1, float2& a2, float2& a3) {
    float2 t0 = cadd(x0, x2), t1 = csub(x0, x2);
    float2 t2 = cadd(x1, x3), t3 = csub(x1, x3);
    float2 pi = make_float2(-t3.y, t3.x);                // +i * t3
    a0 = cadd(t0, t2);
    a1 = cadd(t1, pi);
    a2 = csub(t0, t2);
    a3 = csub(t1, pi);
}

// ---------------- register radix-64 (three fused radix-4 DIF stages) --------
// Local x[r] <-> global position b + r*S, S = 1<<LS, b = g*64S + j (j < S).
// Stage spans 16S, 4S, S.  All twiddles from b = exp(-2*pi*i*j/(64S)).
// HALF: x[32..63] are implicitly zero on entry (zero-padded input).
template<int LS, bool HALF>
__device__ __forceinline__ void fft64_fwd(float2* x, int j) {
    const float C = -6.2831853071795864769f / (float)(1 << (LS + 6));
    float sb, cb;
    __sincosf(C * (float)j, &sb, &cb);
    const float2 b = make_float2(cb, sb);
    // stage A: span 16 local, twiddle (b * rot^c)^m
    #pragma unroll
    for (int c = 0; c < 16; c++) {
        float2 w1 = cmul(b, cROT[c]);
        float2 w2 = cmul(w1, w1), w3 = cmul(w2, w1);
        float2 a0, a1, a2, a3;
        if (HALF) {
            float2 x0 = x[c], x1 = x[c + 16];
            a0 = cadd(x0, x1);
            a1 = make_float2(x0.x + x1.y, x0.y - x1.x);  // x0 - i*x1
            a2 = csub(x0, x1);
            a3 = make_float2(x0.x - x1.y, x0.y + x1.x);  // x0 + i*x1
        } else {
            bf4f(x[c], x[c+16], x[c+32], x[c+48], a0, a1, a2, a3);
        }
        x[c]      = a0;
        x[c + 16] = cmul(a1, w1);
        x[c + 32] = cmul(a2, w2);
        x[c + 48] = cmul(a3, w3);
    }
    const float2 b2 = cmul(b, b);
    const float2 b4 = cmul(b2, b2);
    // stage B: span 4 local, twiddle (b4 * rot^{4c2})^m
    #pragma unroll
    for (int g16 = 0; g16 < 4; g16++) {
        #pragma unroll
        for (int c2 = 0; c2 < 4; c2++) {
            const int i = g16 * 16 + c2;
            float2 w1 = cmul(b4, cROT[4 * c2]);
            float2 w2 = cmul(w1, w1), w3 = cmul(w2, w1);
            float2 a0, a1, a2, a3;
            bf4f(x[i], x[i+4], x[i+8], x[i+12], a0, a1, a2, a3);
            x[i]      = a0;
            x[i + 4]  = cmul(a1, w1);
            x[i + 8]  = cmul(a2, w2);
            x[i + 12] = cmul(a3, w3);
        }
    }
    const float2 b8  = cmul(b4, b4);
    const float2 b16 = cmul(b8, b8);
    float2 w1 = b16;
    float2 w2 = cmul(w1, w1), w3 = cmul(w2, w1);
    // stage C: span 1 local, twiddle b16^m
    #pragma unroll
    for (int m = 0; m < 16; m++) {
        float2 a0, a1, a2, a3;
        bf4f(x[4*m], x[4*m+1], x[4*m+2], x[4*m+3], a0, a1, a2, a3);
        x[4*m]     = a0;
        x[4*m + 1] = cmul(a1, w1);
        x[4*m + 2] = cmul(a2, w2);
        x[4*m + 3] = cmul(a3, w3);
    }
}

template<int LS>
__device__ __forceinline__ void fft64_inv(float2* x, int j) {
    const float C = -6.2831853071795864769f / (float)(1 << (LS + 6));
    float sb, cb;
    __sincosf(C * (float)j, &sb, &cb);
    const float2 b  = make_float2(cb, -sb);              // conj
    const float2 b2 = cmul(b, b);
    const float2 b4 = cmul(b2, b2);
    const float2 b8 = cmul(b4, b4);
    const float2 b16 = cmul(b8, b8);
    // stage C' (undo span-1)
    {
        float2 w1 = b16;
        float2 w2 = cmul(w1, w1), w3 = cmul(w2, w1);
        #pragma unroll
        for (int m = 0; m < 16; m++) {
            float2 z0 = x[4*m];
            float2 z1 = cmul(x[4*m + 1], w1);
            float2 z2 = cmul(x[4*m + 2], w2);
            float2 z3 = cmul(x[4*m + 3], w3);
            bf4i(z0, z1, z2, z3, x[4*m], x[4*m+1], x[4*m+2], x[4*m+3]);
        }
    }
    // stage B' (undo span-4)
    #pragma unroll
    for (int g16 = 0; g16 < 4; g16++) {
        #pragma unroll
        for (int c2 = 0; c2 < 4; c2++) {
            const int i = g16 * 16 + c2;
            float2 w1 = cmul(b4, conjf2(cROT[4 * c2]));
            float2 w2 = cmul(w1, w1), w3 = cmul(w2, w1);
            float2 z0 = x[i];
            float2 z1 = cmul(x[i + 4],  w1);
            float2 z2 = cmul(x[i + 8],  w2);
            float2 z3 = cmul(x[i + 12], w3);
            bf4i(z0, z1, z2, z3, x[i], x[i+4], x[i+8], x[i+12]);
        }
    }
    // stage A' (undo span-16)
    #pragma unroll
    for (int c = 0; c < 16; c++) {
        float2 w1 = cmul(b, conjf2(cROT[c]));
        float2 w2 = cmul(w1, w1), w3 = cmul(w2, w1);
        float2 z0 = x[c];
        float2 z1 = cmul(x[c + 16], w1);
        float2 z2 = cmul(x[c + 32], w2);
        float2 z3 = cmul(x[c + 48], w3);
        bf4i(z0, z1, z2, z3, x[c], x[c+16], x[c+32], x[c+48]);
    }
}

// ---------------- filter MLP stages 1-3 -------------------------------------
__global__ void mlp_kernel(const float* __restrict__ z, const float* __restrict__ freq,
                           const float* __restrict__ W1, const float* __restrict__ b1,
                           const float* __restrict__ W2, const float* __restrict__ b2,
                           const float* __restrict__ W3, const float* __restrict__ b3) {
    __shared__ float zs[4][EMB];
    __shared__ float as[4][FO];
    __shared__ float bs[4][FO];
    const int tid = threadIdx.x;
    const int lg  = tid >> 6;
    const int f   = tid & 63;
    const int l   = blockIdx.x * 4 + lg;

    if (f < EMB) zs[lg][f] = z[l * EMB + f];
    __syncthreads();

    const float fr = freq[f];

    float acc = b1[f];
    #pragma unroll
    for (int e = 0; e < EMB; e++) acc += zs[lg][e] * W1[e * FO + f];
    as[lg][f] = sinf(fr * acc);
    __syncthreads();

    acc = b2[f];
    #pragma unroll
    for (int e = 0; e < FO; e++) acc += as[lg][e] * W2[e * FO + f];
    bs[lg][f] = sinf(fr * acc);
    __syncthreads();

    acc = b3[f];
    #pragma unroll
    for (int e = 0; e < FO; e++) acc += bs[lg][e] * W3[e * FO + f];
    g_S[l * FO + f] = sinf(fr * acc);
}

// ---------------- output projection + exponential modulation ----------------
__global__ void filt_kernel(const float* __restrict__ Wout, const float* __restrict__ t,
                            const float* __restrict__ deltas) {
    __shared__ float Ss[32][FO];
    __shared__ float Ws[FO][128];
    const int tid = threadIdx.x;
    const int l0  = blockIdx.x * 32;
    const int d0  = blockIdx.y * 128;

    for (int i = tid; i < 32 * FO; i += 256)
        Ss[i >> 6][i & 63] = g_S[(l0 + (i >> 6)) * FO + (i & 63)];
    for (int i = tid; i < FO * 128; i += 256)
        Ws[i >> 7][i & 127] = Wout[(i >> 7) * DM + d0 + (i & 127)];
    __syncthreads();

    const int dl  = tid & 127;
    const int lgp = tid >> 7;
    float acc[16];
    #pragma unroll
    for (int i = 0; i < 16; i++) acc[i] = 0.0f;
    #pragma unroll
    for (int f = 0; f < FO; f++) {
        const float w = Ws[f][dl];
        #pragma unroll
        for (int i = 0; i < 16; i++) acc[i] += Ss[lgp * 16 + i][f] * w;
    }
    const int d = d0 + dl;
    const float ad = fabsf(deltas[d]);
    #pragma unroll
    for (int i = 0; i < 16; i++) {
        const int l = l0 + lgp * 16 + i;
        g_k[(size_t)d * LSEQ + l] = acc[i] * (expf(-t[l] * ad) + SHIFT_C);
    }
}

// ---------------- kernel spectrum (+D baked in): 2 radix-64 passes ----------
__global__ void __launch_bounds__(NT, 1)
kf_kernel(const float* __restrict__ Dbias) {
    extern __shared__ float2 d[];
    const int tid = threadIdx.x;
    const int ch  = blockIdx.x;

    const float* krow = g_k + (size_t)ch * LSEQ;

    // P1: stages (6,5,4), S=256, j=tid; elements j + 256r; top half zero
    {
        const int jb = tid + 2 * (tid >> 7);             // PHYS base, stride 260
        float2 x[64];
        #pragma unroll
        for (int r = 0; r < 32; r++)
            x[r] = make_float2(krow[tid + (r << 8)], 0.0f);
        fft64_fwd<8, true>(x, tid);
        #pragma unroll
        for (int r = 0; r < 64; r++) d[jb + 260 * r] = x[r];
    }
    __syncthreads();

    // P2: stages (3,2,1), S=4, j=tid&3, g=tid>>2; elements g*256 + j + 4r
    {
        const int j  = tid & 3;
        const int b0 = (tid >> 2) * 260 + j;             // PHYS: g*256+j+4r -> g*260+j+4r+2*[r>=32]
        float2 x[64];
        #pragma unroll
        for (int r = 0; r < 64; r++) x[r] = d[b0 + 4 * r + ((r >= 32) ? 2 : 0)];
        fft64_fwd<2, false>(x, j);
        #pragma unroll
        for (int r = 0; r < 64; r++) d[b0 + 4 * r + ((r >= 32) ? 2 : 0)] = x[r];
    }
    __syncthreads();

    // P3: stage 0 (twiddle = 1) + bake (spec + D)/N, store to g_Kf
    float2* out = g_Kf + (size_t)ch * NFFT;
    const float sc = 1.0f / (float)NFFT;
    const float Dd = Dbias[ch];
    #pragma unroll
    for (int k = 0; k < 16; k++) {
        const int q  = tid + k * NT;
        const int pp = 4 * q + 2 * (q >> 5);             // PHYS(4q), float4-aligned
        float4 lo = *reinterpret_cast<float4*>(&d[pp]);
        float4 hi = *reinterpret_cast<float4*>(&d[pp + 2]);
        float2 a0, a1, a2, a3;
        bf4f(make_float2(lo.x, lo.y), make_float2(lo.z, lo.w),
             make_float2(hi.x, hi.y), make_float2(hi.z, hi.w), a0, a1, a2, a3);
        float4 o01 = make_float4((a0.x + Dd) * sc, a0.y * sc, (a1.x + Dd) * sc, a1.y * sc);
        float4 o23 = make_float4((a2.x + Dd) * sc, a2.y * sc, (a3.x + Dd) * sc, a3.y * sc);
        reinterpret_cast<float4*>(out)[2 * q]     = o01;
        reinterpret_cast<float4*>(out)[2 * q + 1] = o23;
    }
}

// ---------------- conv: radix-64 fwd x2, stage0*Kf*inv-stage0, inv x2 -------
__global__ void __launch_bounds__(NT, 1)
conv_kernel(const float* __restrict__ x, float* __restrict__ out) {
    extern __shared__ float2 d[];
    const int tid = threadIdx.x;
    const int ch  = blockIdx.x;
    const int p   = blockIdx.y;                          // batch pair

    const float* u0 = x + ((size_t)(2*p)     * DM + ch) * LSEQ;
    const float* u1 = x + ((size_t)(2*p + 1) * DM + ch) * LSEQ;

    const int jb = tid + 2 * (tid >> 7);

    // P1 fwd: stages (6,5,4); pack u0 + i*u1; top half zero
    {
        float2 xv[64];
        #pragma unroll
        for (int r = 0; r < 32; r++) {
            const int i = tid + (r << 8);
            xv[r] = make_float2(u0[i], u1[i]);
        }
        fft64_fwd<8, true>(xv, tid);
        #pragma unroll
        for (int r = 0; r < 64; r++) d[jb + 260 * r] = xv[r];
    }
    __syncthreads();

    const int j  = tid & 3;
    const int b0 = (tid >> 2) * 260 + j;

    // P2 fwd: stages (3,2,1)
    {
        float2 xv[64];
        #pragma unroll
        for (int r = 0; r < 64; r++) xv[r] = d[b0 + 4 * r + ((r >= 32) ? 2 : 0)];
        fft64_fwd<2, false>(xv, j);
        #pragma unroll
        for (int r = 0; r < 64; r++) d[b0 + 4 * r + ((r >= 32) ? 2 : 0)] = xv[r];
    }
    __syncthreads();

    // P3: fwd stage 0 -> pointwise * Kf (D baked in) -> inv stage 0
    const float2* kf = g_Kf + (size_t)ch * NFFT;
    #pragma unroll
    for (int k = 0; k < 16; k++) {
        const int q  = tid + k * NT;
        const int pp = 4 * q + 2 * (q >> 5);
        float4 lo = *reinterpret_cast<float4*>(&d[pp]);
        float4 hi = *reinterpret_cast<float4*>(&d[pp + 2]);
        float2 a0, a1, a2, a3;
        bf4f(make_float2(lo.x, lo.y), make_float2(lo.z, lo.w),
             make_float2(hi.x, hi.y), make_float2(hi.z, hi.w), a0, a1, a2, a3);
        const float4 k01 = reinterpret_cast<const float4*>(kf)[2 * q];
        const float4 k23 = reinterpret_cast<const float4*>(kf)[2 * q + 1];
        a0 = cmul(a0, make_float2(k01.x, k01.y));
        a1 = cmul(a1, make_float2(k01.z, k01.w));
        a2 = cmul(a2, make_float2(k23.x, k23.y));
        a3 = cmul(a3, make_float2(k23.z, k23.w));
        float2 z0, z1, z2, z3;
        bf4i(a0, a1, a2, a3, z0, z1, z2, z3);
        *reinterpret_cast<float4*>(&d[pp])     = make_float4(z0.x, z0.y, z1.x, z1.y);
        *reinterpret_cast<float4*>(&d[pp + 2]) = make_float4(z2.x, z2.y, z3.x, z3.y);
    }
    __syncthreads();

    // P2' inv: undo stages (1,2,3)
    {
        float2 xv[64];
        #pragma unroll
        for (int r = 0; r < 64; r++) xv[r] = d[b0 + 4 * r + ((r >= 32) ? 2 : 0)];
        fft64_inv<2>(xv, j);
        #pragma unroll
        for (int r = 0; r < 64; r++) d[b0 + 4 * r + ((r >= 32) ? 2 : 0)] = xv[r];
    }
    __syncthreads();

    // P1' inv: undo stages (4,5,6); store first LSEQ samples to global
    float* o0 = out + ((size_t)(2*p)     * DM + ch) * LSEQ;
    float* o1 = out + ((size_t)(2*p + 1) * DM + ch) * LSEQ;
    {
        float2 xv[64];
        #pragma unroll
        for (int r = 0; r < 64; r++) xv[r] = d[jb + 260 * r];
        fft64_inv<8>(xv, tid);
        #pragma unroll
        for (int r = 0; r < 32; r++) {
            const int i = tid + (r << 8);
            o0[i] = xv[r].x;
            o1[i] = xv[r].y;
        }
    }
}

// ---------------- launch ----------------------------------------------------
// Input order (metadata): x, z, t, freq, W1, b1, W2, b2, W3, b3, Wout, deltas, D
extern "C" void kernel_launch(void* const* d_in, const int* in_sizes, int n_in,
                              void* d_out, int out_size) {
    (void)in_sizes; (void)n_in; (void)out_size;
    const float* x      = (const float*)d_in[0];
    const float* z      = (const float*)d_in[1];
    const float* t      = (const float*)d_in[2];
    const float* freq   = (const float*)d_in[3];
    const float* W1     = (const float*)d_in[4];
    const float* b1     = (const float*)d_in[5];
    const float* W2     = (const float*)d_in[6];
    const float* b2     = (const float*)d_in[7];
    const float* W3     = (const float*)d_in[8];
    const float* b3     = (const float*)d_in[9];
    const float* Wout   = (const float*)d_in[10];
    const float* deltas = (const float*)d_in[11];
    const float* Dbias  = (const float*)d_in[12];
    float* out = (float*)d_out;

    cudaFuncSetAttribute(kf_kernel,   cudaFuncAttributeMaxDynamicSharedMemorySize, SMEM_BYTES);
    cudaFuncSetAttribute(conv_kernel, cudaFuncAttributeMaxDynamicSharedMemorySize, SMEM_BYTES);

    mlp_kernel<<<LSEQ / 4, 256>>>(z, freq, W1, b1, W2, b2, W3, b3);
    filt_kernel<<<dim3(LSEQ / 32, DM / 128), 256>>>(Wout, t, deltas);
    kf_kernel<<<DM, NT, SMEM_BYTES>>>(Dbias);
    conv_kernel<<<dim3(DM, 2), NT, SMEM_BYTES>>>(x, out);
}

// round 6
// speedup vs baseline: 1.0351x; 1.0351x over previous
#include <cuda_runtime.h>
#include <math.h>

// Problem constants
#define LSEQ 8192
#define NFFT 16384          // 2*LSEQ = 32*32*16
#define DM   768
#define EMB  33
#define FO   64
#define SHIFT_C 0.05f
#define NT   512            // FFT threads per CTA

// Pad 1 float2 per 16: PHYS(i) = i + (i>>4).
// Verified conflict-free (per 16-lane LDS.64 phase) for all passes:
//  P1: lanes consecutive j          -> residues distinct
//  P2: addr 544g + j2 + 17r         -> residue (j2 + r) mod 16, j2 distinct
//  P3: addr 17q + c                 -> residue (q + c) mod 16, q distinct
#define DPAD 17408                                       // PHYS(16383)=17406
#define SMEM_BYTES (DPAD * (int)sizeof(float2))          // 139264 B

// ---------------- scratch (device globals: no allocations allowed) ----------
__device__ float  g_S[LSEQ * FO];                        // post-MLP activations
__device__ float  g_k[DM * LSEQ];                        // filter k[d][l]
__device__ __align__(16) float2 g_Kf[(size_t)DM * NFFT]; // (spectrum + D)/N, scrambled

// e^{-2*pi*i*c/32}, c = 0..7
__constant__ float2 cR32[8] = {
    { 1.0f, 0.0f },
    { 0.98078528040323044f, -0.19509032201612827f },
    { 0.92387953251128674f, -0.38268343236508977f },
    { 0.83146961230254524f, -0.55557023301960222f },
    { 0.70710678118654752f, -0.70710678118654752f },
    { 0.55557023301960222f, -0.83146961230254524f },
    { 0.38268343236508977f, -0.92387953251128674f },
    { 0.19509032201612827f, -0.98078528040323044f }
};
// e^{-2*pi*i*c/16}, c = 0..3
__constant__ float2 cR16[4] = {
    { 1.0f, 0.0f },
    { 0.92387953251128674f, -0.38268343236508977f },
    { 0.70710678118654752f, -0.70710678118654752f },
    { 0.38268343236508977f, -0.92387953251128674f }
};
#define R8X 0.70710678118654752f

// ---------------- complex helpers ----------------
__device__ __forceinline__ float2 cadd(float2 a, float2 b){ return make_float2(a.x+b.x, a.y+b.y); }
__device__ __forceinline__ float2 csub(float2 a, float2 b){ return make_float2(a.x-b.x, a.y-b.y); }
__device__ __forceinline__ float2 cmul(float2 a, float2 b){
    return make_float2(a.x*b.x - a.y*b.y, a.x*b.y + a.y*b.x);
}
__device__ __forceinline__ float2 conjf2(float2 a){ return make_float2(a.x, -a.y); }

// radix-4 DIF forward core (no twiddle)
__device__ __forceinline__ void bf4f(float2 x0, float2 x1, float2 x2, float2 x3,
                                     float2& a0, float2& a1, float2& a2, float2& a3) {
    float2 t0 = cadd(x0, x2), t1 = csub(x0, x2);
    float2 t2 = cadd(x1, x3), t3 = csub(x1, x3);
    float2 mi = make_float2(t3.y, -t3.x);                // -i * t3
    a0 = cadd(t0, t2);
    a1 = cadd(t1, mi);
    a2 = csub(t0, t2);
    a3 = csub(t1, mi);
}
// radix-4 inverse core (unscaled)
__device__ __forceinline__ void bf4i(float2 x0, float2 x1, float2 x2, float2 x3,
                                     float2& a0, float2& a1, float2& a2, float2& a3) {
    float2 t0 = cadd(x0, x2), t1 = csub(x0, x2);
    float2 t2 = cadd(x1, x3), t3 = csub(x1, x3);
    float2 pi = make_float2(-t3.y, t3.x);                // +i * t3
    a0 = cadd(t0, t2);
    a1 = cadd(t1, pi);
    a2 = csub(t0, t2);
    a3 = csub(t1, pi);
}

// ---------------- register radix-32 (4*4*2 DIF), external span S = 1<<LS ----
// x[r] <-> global b + r*S.  All twiddles from b = exp(-2*pi*i*j/(32S)).
// HALF: x[16..31] implicitly zero on entry.
template<int LS, bool HALF>
__device__ __forceinline__ void fft32_fwd(float2* x, int j) {
    const float C = -6.2831853071795864769f / (float)(1 << (LS + 5));
    float sb, cb;
    __sincosf(C * (float)j, &sb, &cb);
    const float2 b = make_float2(cb, sb);
    // stage A: span 8
    #pragma unroll
    for (int c = 0; c < 8; c++) {
        float2 w1 = cmul(b, cR32[c]);
        float2 w2 = cmul(w1, w1), w3 = cmul(w2, w1);
        float2 a0, a1, a2, a3;
        if (HALF) {
            float2 x0 = x[c], x1 = x[c + 8];
            a0 = cadd(x0, x1);
            a1 = make_float2(x0.x + x1.y, x0.y - x1.x);  // x0 - i*x1
            a2 = csub(x0, x1);
            a3 = make_float2(x0.x - x1.y, x0.y + x1.x);  // x0 + i*x1
        } else {
            bf4f(x[c], x[c+8], x[c+16], x[c+24], a0, a1, a2, a3);
        }
        x[c]      = a0;
        x[c + 8]  = cmul(a1, w1);
        x[c + 16] = cmul(a2, w2);
        x[c + 24] = cmul(a3, w3);
    }
    const float2 b2 = cmul(b, b);
    const float2 b4 = cmul(b2, b2);
    const float2 b4r = cmul(b4, make_float2(R8X, -R8X)); // b4 * e^{-i pi/4}
    // stage B: span 2
    #pragma unroll
    for (int g = 0; g < 4; g++) {
        #pragma unroll
        for (int c2 = 0; c2 < 2; c2++) {
            const int i = 8 * g + c2;
            float2 w1 = (c2 == 0) ? b4 : b4r;
            float2 w2 = cmul(w1, w1), w3 = cmul(w2, w1);
            float2 a0, a1, a2, a3;
            bf4f(x[i], x[i+2], x[i+4], x[i+6], a0, a1, a2, a3);
            x[i]     = a0;
            x[i + 2] = cmul(a1, w1);
            x[i + 4] = cmul(a2, w2);
            x[i + 6] = cmul(a3, w3);
        }
    }
    const float2 b8  = cmul(b4, b4);
    const float2 b16 = cmul(b8, b8);
    // stage C: radix-2, span 1
    #pragma unroll
    for (int m = 0; m < 16; m++) {
        float2 x0 = x[2*m], x1 = x[2*m + 1];
        x[2*m]     = cadd(x0, x1);
        x[2*m + 1] = cmul(csub(x0, x1), b16);
    }
}

// Inverse (unscaled, gain 32).  HALFOUT: only outputs r<16 are produced.
template<int LS, bool HALFOUT>
__device__ __forceinline__ void fft32_inv(float2* x, int j) {
    const float C = -6.2831853071795864769f / (float)(1 << (LS + 5));
    float sb, cb;
    __sincosf(C * (float)j, &sb, &cb);
    const float2 b   = make_float2(cb, -sb);             // conj
    const float2 b2  = cmul(b, b);
    const float2 b4  = cmul(b2, b2);
    const float2 b8  = cmul(b4, b4);
    const float2 b16 = cmul(b8, b8);
    // stage C'
    #pragma unroll
    for (int m = 0; m < 16; m++) {
        float2 z1 = cmul(x[2*m + 1], b16);
        float2 x0 = x[2*m];
        x[2*m]     = cadd(x0, z1);
        x[2*m + 1] = csub(x0, z1);
    }
    // stage B'
    const float2 b4r = cmul(b4, make_float2(R8X, R8X));  // b4 * e^{+i pi/4}
    #pragma unroll
    for (int g = 0; g < 4; g++) {
        #pragma unroll
        for (int c2 = 0; c2 < 2; c2++) {
            const int i = 8 * g + c2;
            float2 w1 = (c2 == 0) ? b4 : b4r;
            float2 w2 = cmul(w1, w1), w3 = cmul(w2, w1);
            float2 z0 = x[i];
            float2 z1 = cmul(x[i + 2], w1);
            float2 z2 = cmul(x[i + 4], w2);
            float2 z3 = cmul(x[i + 6], w3);
            bf4i(z0, z1, z2, z3, x[i], x[i+2], x[i+4], x[i+6]);
        }
    }
    // stage A'
    #pragma unroll
    for (int c = 0; c < 8; c++) {
        float2 w1 = cmul(b, conjf2(cR32[c]));
        float2 w2 = cmul(w1, w1), w3 = cmul(w2, w1);
        float2 z0 = x[c];
        float2 z1 = cmul(x[c + 8],  w1);
        float2 z2 = cmul(x[c + 16], w2);
        float2 z3 = cmul(x[c + 24], w3);
        if (HALFOUT) {
            float2 t0 = cadd(z0, z2), t1 = csub(z0, z2);
            float2 t2 = cadd(z1, z3), t3 = csub(z1, z3);
            float2 pi = make_float2(-t3.y, t3.x);
            x[c]     = cadd(t0, t2);
            x[c + 8] = cadd(t1, pi);
        } else {
            bf4i(z0, z1, z2, z3, x[c], x[c+8], x[c+16], x[c+24]);
        }
    }
}

// ---------------- 16-point cores, all-constant twiddles (S=1 level) ---------
__device__ __forceinline__ void fft16c_fwd(float2* x) {
    #pragma unroll
    for (int c = 0; c < 4; c++) {
        float2 w1 = cR16[c];
        float2 w2 = cmul(w1, w1), w3 = cmul(w2, w1);
        float2 a0, a1, a2, a3;
        bf4f(x[c], x[c+4], x[c+8], x[c+12], a0, a1, a2, a3);
        x[c]      = a0;
        x[c + 4]  = cmul(a1, w1);
        x[c + 8]  = cmul(a2, w2);
        x[c + 12] = cmul(a3, w3);
    }
    #pragma unroll
    for (int m = 0; m < 4; m++) {
        float2 a0, a1, a2, a3;
        bf4f(x[4*m], x[4*m+1], x[4*m+2], x[4*m+3], a0, a1, a2, a3);
        x[4*m] = a0; x[4*m+1] = a1; x[4*m+2] = a2; x[4*m+3] = a3;
    }
}
__device__ __forceinline__ void fft16c_inv(float2* x) {
    #pragma unroll
    for (int m = 0; m < 4; m++) {
        float2 a0, a1, a2, a3;
        bf4i(x[4*m], x[4*m+1], x[4*m+2], x[4*m+3], a0, a1, a2, a3);
        x[4*m] = a0; x[4*m+1] = a1; x[4*m+2] = a2; x[4*m+3] = a3;
    }
    #pragma unroll
    for (int c = 0; c < 4; c++) {
        float2 w1 = conjf2(cR16[c]);
        float2 w2 = cmul(w1, w1), w3 = cmul(w2, w1);
        float2 z1 = cmul(x[c + 4],  w1);
        float2 z2 = cmul(x[c + 8],  w2);
        float2 z3 = cmul(x[c + 12], w3);
        bf4i(x[c], z1, z2, z3, x[c], x[c+4], x[c+8], x[c+12]);
    }
}

// ---------------- filter MLP stages 1-3 -------------------------------------
__global__ void mlp_kernel(const float* __restrict__ z, const float* __restrict__ freq,
                           const float* __restrict__ W1, const float* __restrict__ b1,
                           const float* __restrict__ W2, const float* __restrict__ b2,
                           const float* __restrict__ W3, const float* __restrict__ b3) {
    __shared__ float zs[4][EMB];
    __shared__ float as[4][FO];
    __shared__ float bs[4][FO];
    const int tid = threadIdx.x;
    const int lg  = tid >> 6;
    const int f   = tid & 63;
    const int l   = blockIdx.x * 4 + lg;

    if (f < EMB) zs[lg][f] = z[l * EMB + f];
    __syncthreads();

    const float fr = freq[f];

    float acc = b1[f];
    #pragma unroll
    for (int e = 0; e < EMB; e++) acc += zs[lg][e] * W1[e * FO + f];
    as[lg][f] = sinf(fr * acc);
    __syncthreads();

    acc = b2[f];
    #pragma unroll
    for (int e = 0; e < FO; e++) acc += as[lg][e] * W2[e * FO + f];
    bs[lg][f] = sinf(fr * acc);
    __syncthreads();

    acc = b3[f];
    #pragma unroll
    for (int e = 0; e < FO; e++) acc += bs[lg][e] * W3[e * FO + f];
    g_S[l * FO + f] = sinf(fr * acc);
}

// ---------------- output projection + exponential modulation ----------------
__global__ void filt_kernel(const float* __restrict__ Wout, const float* __restrict__ t,
                            const float* __restrict__ deltas) {
    __shared__ float Ss[32][FO];
    __shared__ float Ws[FO][128];
    const int tid = threadIdx.x;
    const int l0  = blockIdx.x * 32;
    const int d0  = blockIdx.y * 128;

    for (int i = tid; i < 32 * FO; i += 256)
        Ss[i >> 6][i & 63] = g_S[(l0 + (i >> 6)) * FO + (i & 63)];
    for (int i = tid; i < FO * 128; i += 256)
        Ws[i >> 7][i & 127] = Wout[(i >> 7) * DM + d0 + (i & 127)];
    __syncthreads();

    const int dl  = tid & 127;
    const int lgp = tid >> 7;
    float acc[16];
    #pragma unroll
    for (int i = 0; i < 16; i++) acc[i] = 0.0f;
    #pragma unroll
    for (int f = 0; f < FO; f++) {
        const float w = Ws[f][dl];
        #pragma unroll
        for (int i = 0; i < 16; i++) acc[i] += Ss[lgp * 16 + i][f] * w;
    }
    const int d = d0 + dl;
    const float ad = fabsf(deltas[d]);
    #pragma unroll
    for (int i = 0; i < 16; i++) {
        const int l = l0 + lgp * 16 + i;
        g_k[(size_t)d * LSEQ + l] = acc[i] * (expf(-t[l] * ad) + SHIFT_C);
    }
}

// ---------------- kernel spectrum (+D baked in) -----------------------------
__global__ void __launch_bounds__(NT, 1)
kf_kernel(const float* __restrict__ Dbias) {
    extern __shared__ float2 d[];
    const int tid = threadIdx.x;
    const int ch  = blockIdx.x;

    const float* krow = g_k + (size_t)ch * LSEQ;
    const int jb = tid + (tid >> 4);                     // PHYS(tid)

    // P1: radix-32, S=512; top half zero
    {
        float2 xv[32];
        #pragma unroll
        for (int r = 0; r < 16; r++)
            xv[r] = make_float2(krow[tid + (r << 9)], 0.0f);
        fft32_fwd<9, true>(xv, tid);
        #pragma unroll
        for (int r = 0; r < 32; r++) d[jb + 544 * r] = xv[r];
    }
    __syncthreads();

    const int j2 = tid & 15;
    const int b0 = (tid >> 4) * 544 + j2;

    // P2: radix-32, S=16
    {
        float2 xv[32];
        #pragma unroll
        for (int r = 0; r < 32; r++) xv[r] = d[b0 + 17 * r];
        fft32_fwd<4, false>(xv, j2);
        #pragma unroll
        for (int r = 0; r < 32; r++) d[b0 + 17 * r] = xv[r];
    }
    __syncthreads();

    // P3: const-twiddle fwd16 + bake (spec + D)/N, store to g_Kf
    float2* outp = g_Kf + (size_t)ch * NFFT;
    const float sc = 1.0f / (float)NFFT;
    const float Dd = Dbias[ch];
    #pragma unroll
    for (int k = 0; k < 2; k++) {
        const int q  = tid + k * NT;
        const int pb = 17 * q;                           // PHYS(16q)
        float2 xv[16];
        #pragma unroll
        for (int r = 0; r < 16; r++) xv[r] = d[pb + r];
        fft16c_fwd(xv);
        float4* o4 = reinterpret_cast<float4*>(outp + 16 * q);
        #pragma unroll
        for (int i = 0; i < 8; i++) {
            o4[i] = make_float4((xv[2*i].x + Dd) * sc, xv[2*i].y * sc,
                                (xv[2*i+1].x + Dd) * sc, xv[2*i+1].y * sc);
        }
    }
}

// ---------------- conv ------------------------------------------------------
__global__ void __launch_bounds__(NT, 1)
conv_kernel(const float* __restrict__ x, float* __restrict__ out) {
    extern __shared__ float2 d[];
    const int tid = threadIdx.x;
    const int ch  = blockIdx.x;
    const int p   = blockIdx.y;                          // batch pair

    const float* u0 = x + ((size_t)(2*p)     * DM + ch) * LSEQ;
    const float* u1 = x + ((size_t)(2*p + 1) * DM + ch) * LSEQ;

    const int jb = tid + (tid >> 4);

    // P1 fwd: radix-32, S=512; pack u0 + i*u1; top half zero
    {
        float2 xv[32];
        #pragma unroll
        for (int r = 0; r < 16; r++) {
            const int i = tid + (r << 9);
            xv[r] = make_float2(u0[i], u1[i]);
        }
        fft32_fwd<9, true>(xv, tid);
        #pragma unroll
        for (int r = 0; r < 32; r++) d[jb + 544 * r] = xv[r];
    }
    __syncthreads();

    const int j2 = tid & 15;
    const int b0 = (tid >> 4) * 544 + j2;

    // P2 fwd: radix-32, S=16
    {
        float2 xv[32];
        #pragma unroll
        for (int r = 0; r < 32; r++) xv[r] = d[b0 + 17 * r];
        fft32_fwd<4, false>(xv, j2);
        #pragma unroll
        for (int r = 0; r < 32; r++) d[b0 + 17 * r] = xv[r];
    }
    __syncthreads();

    // P3: const-twiddle fwd16 -> * Kf (D baked in) -> const-twiddle inv16
    const float2* kf = g_Kf + (size_t)ch * NFFT;
    #pragma unroll
    for (int k = 0; k < 2; k++) {
        const int q  = tid + k * NT;
        const int pb = 17 * q;
        float4 kreg[8];
        const float4* kf4 = reinterpret_cast<const float4*>(kf + 16 * q);
        #pragma unroll
        for (int i = 0; i < 8; i++) kreg[i] = kf4[i];    // prefetch over fwd16
        float2 xv[16];
        #pragma unroll
        for (int r = 0; r < 16; r++) xv[r] = d[pb + r];
        fft16c_fwd(xv);
        #pragma unroll
        for (int i = 0; i < 8; i++) {
            xv[2*i]   = cmul(xv[2*i],   make_float2(kreg[i].x, kreg[i].y));
            xv[2*i+1] = cmul(xv[2*i+1], make_float2(kreg[i].z, kreg[i].w));
        }
        fft16c_inv(xv);
        #pragma unroll
        for (int r = 0; r < 16; r++) d[pb + r] = xv[r];
    }
    __syncthreads();

    // P2' inv
    {
        float2 xv[32];
        #pragma unroll
        for (int r = 0; r < 32; r++) xv[r] = d[b0 + 17 * r];
        fft32_inv<4, false>(xv, j2);
        #pragma unroll
        for (int r = 0; r < 32; r++) d[b0 + 17 * r] = xv[r];
    }
    __syncthreads();

    // P1' inv: half output, direct global store
    float* o0 = out + ((size_t)(2*p)     * DM + ch) * LSEQ;
    float* o1 = out + ((size_t)(2*p + 1) * DM + ch) * LSEQ;
    {
        float2 xv[32];
        #pragma unroll
        for (int r = 0; r < 32; r++) xv[r] = d[jb + 544 * r];
        fft32_inv<9, true>(xv, tid);
        #pragma unroll
        for (int r = 0; r < 16; r++) {
            const int i = tid + (r << 9);
            o0[i] = xv[r].x;
            o1[i] = xv[r].y;
        }
    }
}

// ---------------- launch ----------------------------------------------------
// Input order (metadata): x, z, t, freq, W1, b1, W2, b2, W3, b3, Wout, deltas, D
extern "C" void kernel_launch(void* const* d_in, const int* in_sizes, int n_in,
                              void* d_out, int out_size) {
    (void)in_sizes; (void)n_in; (void)out_size;
    const float* x      = (const float*)d_in[0];
    const float* z      = (const float*)d_in[1];
    const float* t      = (const float*)d_in[2];
    const float* freq   = (const float*)d_in[3];
    const float* W1     = (const float*)d_in[4];
    const float* b1     = (const float*)d_in[5];
    const float* W2     = (const float*)d_in[6];
    const float* b2     = (const float*)d_in[7];
    const float* W3     = (const float*)d_in[8];
    const float* b3     = (const float*)d_in[9];
    const float* Wout   = (const float*)d_in[10];
    const float* deltas = (const float*)d_in[11];
    const float* Dbias  = (const float*)d_in[12];
    float* out = (float*)d_out;

    cudaFuncSetAttribute(kf_kernel,   cudaFuncAttributeMaxDynamicSharedMemorySize, SMEM_BYTES);
    cudaFuncSetAttribute(conv_kernel, cudaFuncAttributeMaxDynamicSharedMemorySize, SMEM_BYTES);

    mlp_kernel<<<LSEQ / 4, 256>>>(z, freq, W1, b1, W2, b2, W3, b3);
    filt_kernel<<<dim3(LSEQ / 32, DM / 128), 256>>>(Wout, t, deltas);
    kf_kernel<<<DM, NT, SMEM_BYTES>>>(Dbias);
    conv_kernel<<<dim3(DM, 2), NT, SMEM_BYTES>>>(x, out);
}